// round 1
// baseline (speedup 1.0000x reference)
#include <cuda_runtime.h>
#include <cstdint>

#define NW 10
#define DIM 1024
#define HID 64

// W = U[:, :64]; stored column-major-by-c: WG[c*DIM + i] = (Re, Im) of amplitude i of column c.
__device__ float2 WG[HID * DIM];

__device__ __forceinline__ void gate1q(float2* psi, int tid, int bit,
    float g00x, float g00y, float g01x, float g01y,
    float g10x, float g10y, float g11x, float g11y)
{
    const int lowmask = bit - 1;
    const int i0 = ((tid & ~lowmask) << 1) | (tid & lowmask);
    const int i1 = i0 | bit;
    const float2 a = psi[i0], b = psi[i1];
    float2 n0, n1;
    n0.x = g00x*a.x - g00y*a.y + g01x*b.x - g01y*b.y;
    n0.y = g00x*a.y + g00y*a.x + g01x*b.y + g01y*b.x;
    n1.x = g10x*a.x - g10y*a.y + g11x*b.x - g11y*b.y;
    n1.y = g10x*a.y + g10y*a.x + g11x*b.y + g11y*b.x;
    psi[i0] = n0; psi[i1] = n1;
}

// One block per basis column c: apply the full gate sequence to e_c, write W[:,c].
__global__ void qsa_circuit(const float* __restrict__ rx0,
                            const float* __restrict__ ry0,
                            const float* __restrict__ ry1)
{
    __shared__ float2 psi[DIM];
    const int tid = threadIdx.x;   // 512 threads
    const int c = blockIdx.x;      // 0..63

    psi[tid]       = make_float2(0.f, 0.f);
    psi[tid + 512] = make_float2(0.f, 0.f);
    __syncthreads();
    if (tid == 0) psi[c] = make_float2(1.f, 0.f);
    __syncthreads();

    // for j: RX(rx0[j]) then RY(ry0[j]) on qubit j (qubit j = bit (9-j), MSB-first)
    for (int j = 0; j < NW; j++) {
        const int bit = 1 << (NW - 1 - j);
        float s, cc;
        sincosf(0.5f * rx0[j], &s, &cc);
        // RX = [[c, -i s], [-i s, c]]
        gate1q(psi, tid, bit, cc, 0.f, 0.f, -s, 0.f, -s, cc, 0.f);
        __syncthreads();
        sincosf(0.5f * ry0[j], &s, &cc);
        // RY = [[c, -s], [s, c]]
        gate1q(psi, tid, bit, cc, 0.f, -s, 0.f, s, 0.f, cc, 0.f);
        __syncthreads();
    }
    // CNOT ring: control qubit j, target qubit (j+1)%10
    for (int j = 0; j < NW; j++) {
        const int cbit = 1 << (NW - 1 - j);
        const int tbit = 1 << (NW - 1 - ((j + 1) % NW));
        #pragma unroll
        for (int rep = 0; rep < 2; rep++) {
            const int i = tid + rep * 512;
            if ((i & cbit) && !(i & tbit)) {
                const float2 t = psi[i];
                psi[i] = psi[i | tbit];
                psi[i | tbit] = t;
            }
        }
        __syncthreads();
    }
    // final RY layer
    for (int j = 0; j < NW; j++) {
        const int bit = 1 << (NW - 1 - j);
        float s, cc;
        sincosf(0.5f * ry1[j], &s, &cc);
        gate1q(psi, tid, bit, cc, 0.f, -s, 0.f, s, 0.f, cc, 0.f);
        __syncthreads();
    }

    WG[c * DIM + tid]       = psi[tid];
    WG[c * DIM + tid + 512] = psi[tid + 512];
}

struct SmemA {
    float  Yt[64][64];   // [c][m]  normalized inputs, transposed  (16 KB)
    float2 Ws[64][64];   // [c][n]  W tile                          (32 KB)
};
union SmemU {
    SmemA s;
    float Q[64][129];    // folded probabilities, padded (33 KB) — reuses the same smem
};

// 64 tokens per block, 256 threads (16x16), 4x4 register tiles, K=64.
__global__ __launch_bounds__(256) void qsa_main(const float* __restrict__ x,
                                                float* __restrict__ out)
{
    __shared__ SmemU sm;
    const int tid = threadIdx.x;
    const int m0 = blockIdx.x * 64;

    // ---- load + L2-normalize 64 tokens; store transposed Yt[c][m] ----
    {
        const int m = tid >> 2;       // 0..63
        const int cg = tid & 3;       // 16-feature chunk
        const float4* xr = reinterpret_cast<const float4*>(
            x + (size_t)(m0 + m) * HID + cg * 16);
        float4 v[4];
        #pragma unroll
        for (int u = 0; u < 4; u++) v[u] = xr[u];
        float ssq = 0.f;
        #pragma unroll
        for (int u = 0; u < 4; u++)
            ssq += v[u].x*v[u].x + v[u].y*v[u].y + v[u].z*v[u].z + v[u].w*v[u].w;
        ssq += __shfl_xor_sync(0xffffffffu, ssq, 1);
        ssq += __shfl_xor_sync(0xffffffffu, ssq, 2);
        const float rn = rsqrtf(ssq);
        #pragma unroll
        for (int u = 0; u < 4; u++) {
            sm.s.Yt[cg*16 + 4*u + 0][m] = v[u].x * rn;
            sm.s.Yt[cg*16 + 4*u + 1][m] = v[u].y * rn;
            sm.s.Yt[cg*16 + 4*u + 2][m] = v[u].z * rn;
            sm.s.Yt[cg*16 + 4*u + 3][m] = v[u].w * rn;
        }
    }

    const int txq = tid & 15;   // n direction
    const int tyq = tid >> 4;   // m direction

    // q accumulators: j = par*64 + (txq*4+nn), par = tile parity
    float qacc[2][4][4];
    #pragma unroll
    for (int p = 0; p < 2; p++)
        #pragma unroll
        for (int a = 0; a < 4; a++)
            #pragma unroll
            for (int b = 0; b < 4; b++) qacc[p][a][b] = 0.f;

    for (int tt = 0; tt < 16; tt++) {
        __syncthreads();
        // load W tile: Ws[c][n] <- WG[c*DIM + tt*64 + n], fully coalesced float4s
        {
            float4* dst = reinterpret_cast<float4*>(&sm.s.Ws[0][0]);
            #pragma unroll
            for (int u = 0; u < 8; u++) {
                const int f4 = tid + u * 256;     // 0..2047
                const int c = f4 >> 5;            // 32 float4 per row
                const int col = f4 & 31;
                const float4* srow = reinterpret_cast<const float4*>(WG + c * DIM + tt * 64);
                dst[f4] = srow[col];
            }
        }
        __syncthreads();

        float are[4][4], aim[4][4];
        #pragma unroll
        for (int a = 0; a < 4; a++)
            #pragma unroll
            for (int b = 0; b < 4; b++) { are[a][b] = 0.f; aim[a][b] = 0.f; }

        #pragma unroll 8
        for (int k = 0; k < 64; k++) {
            const float4 yv = *reinterpret_cast<const float4*>(&sm.s.Yt[k][tyq << 2]);
            const float4 wa = *reinterpret_cast<const float4*>(&sm.s.Ws[k][txq << 2]);
            const float4 wb = *reinterpret_cast<const float4*>(&sm.s.Ws[k][(txq << 2) + 2]);
            const float y[4]  = {yv.x, yv.y, yv.z, yv.w};
            const float wr[4] = {wa.x, wa.z, wb.x, wb.z};
            const float wi[4] = {wa.y, wa.w, wb.y, wb.w};
            #pragma unroll
            for (int mm = 0; mm < 4; mm++)
                #pragma unroll
                for (int nn = 0; nn < 4; nn++) {
                    are[mm][nn] = fmaf(y[mm], wr[nn], are[mm][nn]);
                    aim[mm][nn] = fmaf(y[mm], wi[nn], aim[mm][nn]);
                }
        }

        // fold |a|^2 into q (low-7-bit groups): j = (tt&1)*64 + local n
        const int par = tt & 1;
        #pragma unroll
        for (int mm = 0; mm < 4; mm++)
            #pragma unroll
            for (int nn = 0; nn < 4; nn++) {
                const float p = fmaf(are[mm][nn], are[mm][nn],
                                     aim[mm][nn] * aim[mm][nn]);
                qacc[par][mm][nn] += p;
            }
    }

    // ---- spill q to (reused) smem ----
    __syncthreads();
    #pragma unroll
    for (int par = 0; par < 2; par++)
        #pragma unroll
        for (int mm = 0; mm < 4; mm++)
            #pragma unroll
            for (int nn = 0; nn < 4; nn++)
                sm.Q[(tyq << 2) + mm][par * 64 + (txq << 2) + nn] = qacc[par][mm][nn];
    __syncthreads();

    // ---- out[m][k] = sum_j (-1)^popc(j & (k+1)) * q[m][j] ----
    {
        const int m = tid >> 2;     // 0..63
        const int kg = tid & 3;     // 16 outputs each
        const float* qrow = sm.Q[m];
        #pragma unroll 1
        for (int kk = 0; kk < 16; kk++) {
            const int k = kg * 16 + kk;
            const int mask = k + 1;
            float acc = 0.f;
            #pragma unroll 16
            for (int j = 0; j < 128; j++) {
                const float v = qrow[j];
                acc += (__popc(j & mask) & 1) ? -v : v;
            }
            out[(size_t)(m0 + m) * HID + k] = acc;
        }
    }
}

extern "C" void kernel_launch(void* const* d_in, const int* in_sizes, int n_in,
                              void* d_out, int out_size)
{
    const float* x   = (const float*)d_in[0];
    const float* rx0 = (const float*)d_in[1];
    const float* ry0 = (const float*)d_in[2];
    const float* ry1 = (const float*)d_in[3];
    float* out = (float*)d_out;

    const int M = in_sizes[0] / HID;        // 16384 tokens

    qsa_circuit<<<HID, 512>>>(rx0, ry0, ry1);   // materialize W (512 KB device global)
    qsa_main<<<M / 64, 256>>>(x, out);          // GEMM + |.|^2 fold + sign transform
}